// round 4
// baseline (speedup 1.0000x reference)
#include <cuda_runtime.h>

// Pooled attention embedding bag, GB300 (sm_103a).
//   B=8192 bags, L<=56 items/bag (via offsets), D=64, ATT=64, K=4.
//   out[b,k,:] = sum_i softmax_i( tanh(E_i @ Wp^T + b) @ att_h )[k] * E_i
//
// R4 design:
//  * 4 bags per CTA (grid B/4) -> weight staging amortized 4x.
//  * proj_w transposed ONCE (prep kernel) into __device__ g_Wt; CTAs copy it
//    into smem with conflict-free coalesced float4s (no per-CTA transpose).
//  * GEMM: 8 items x 4 att per thread, a-pair packed fma.rn.f32x2,
//    bank-friendly lane interleaving (lanes consecutive in a for W loads,
//    consecutive in item for E loads). Two a-passes reuse accumulators.
//  * H never stored: att = H @ att_h fused into the GEMM epilogue via
//    4 butterfly shuffles over the 16 a-quad lanes.
//  * Warp-parallel ragged softmax; float4 pooling; coalesced float4 output.

namespace {
constexpr int Dm    = 64;
constexpr int ATTm  = 64;
constexpr int KN    = 4;
constexpr int NB    = 4;              // bags per CTA
constexpr int MAXI  = 56;             // items per bag staged (7 octets)
constexpr int NITEM = NB * MAXI;      // 224
constexpr int PAD   = 68;             // padded row (floats), 16B-aligned rows
constexpr int NT    = 224;            // 7 warps
constexpr int SMEM_FLOATS = 64*PAD    // Wt [d][a] (transposed weights)
                          + NITEM*PAD // E  [item][d]
                          + NITEM*KN  // At [item][k]
                          + KN*PAD    // AhT[k][a]
                          + ATTm      // Pb
                          + 16;       // Red [bag][k] = 1/sum
}

__device__ int   g_idx_is64;      // 1 if index/offset buffers are int64
__device__ float g_Wt[64 * 64];   // g_Wt[d*64+a] = projw[a*64+d]

using ull = unsigned long long;

__device__ __forceinline__ float tanh_fast(float x) {
    float y;
    asm("tanh.approx.f32 %0, %1;" : "=f"(y) : "f"(x));
    return y;
}
// packed dual-FMA: d.lo += a.lo*b.lo ; d.hi += a.hi*b.hi (bit-exact fp32)
__device__ __forceinline__ void ffma2(ull& d, ull a, ull b) {
    asm("fma.rn.f32x2 %0, %1, %2, %0;" : "+l"(d) : "l"(a), "l"(b));
}
__device__ __forceinline__ ull bcast2(float x) {
    ull r;
    asm("mov.b64 %0, {%1, %1};" : "=l"(r) : "f"(x));
    return r;
}
__device__ __forceinline__ void unpack2(float& lo, float& hi, ull v) {
    asm("mov.b64 {%0, %1}, %2;" : "=f"(lo), "=f"(hi) : "l"(v));
}
__device__ __forceinline__ long long ld_idx(const void* p, long long i, int is64) {
    return is64 ? ((const long long*)p)[i]
                : (long long)((const int*)p)[i];
}

// One block: transpose proj_w into g_Wt, and detect index dtype (thread 0).
extern "C" __global__ void prep_kernel(const float* __restrict__ projw,
                                       const void* __restrict__ input_,
                                       const void* __restrict__ offsets,
                                       long long nnz, int nseg, long long vocab) {
    int t = threadIdx.x;
    for (int p = t; p < 64 * 64; p += 256) {
        int a = p >> 6, d = p & 63;          // coalesced read of projw
        g_Wt[d * 64 + a] = projw[p];
    }
    if (t == 0) {
        bool ok = true;
        const long long* o64 = (const long long*)offsets;
        int no = nseg < 4 ? nseg : 4;
        long long prev = -1;
        for (int i = 0; i < no; ++i) {
            long long v = o64[i];
            if (v < 0 || v > nnz || v < prev) ok = false;
            prev = v;
        }
        const long long* in64 = (const long long*)input_;
        long long ni = nnz < 8 ? nnz : 8;
        for (long long i = 0; i < ni; ++i) {
            long long v = in64[i];
            if (v < 0 || v >= vocab) ok = false;
        }
        g_idx_is64 = ok ? 1 : 0;
    }
}

extern "C" __global__ void __launch_bounds__(NT, 2)
pooled_att_kernel(const void*  __restrict__ input_,
                  const void*  __restrict__ offsets,
                  const float* __restrict__ emb,
                  const float* __restrict__ projb,   // [ATT]
                  const float* __restrict__ atth,    // [ATT, K] row-major
                  float*       __restrict__ out,     // [B, K, D]
                  int nseg, long long nnz)
{
    extern __shared__ float sm[];
    float* Wt  = sm;                    // [64][PAD]  Wt[d*PAD+a]
    float* E   = Wt  + 64*PAD;          // [NITEM][PAD]
    float* At  = E   + NITEM*PAD;       // [NITEM][KN]
    float* AhT = At  + NITEM*KN;        // [KN][PAD]  AhT[k*PAD+a] = atth[a*KN+k]
    float* Pb  = AhT + KN*PAD;          // [ATT]
    float* Red = Pb  + ATTm;            // [NB][KN] = 1/sum

    __shared__ long long s_start[NB];
    __shared__ int       s_cnt[NB];

    const int tid  = threadIdx.x;
    const int is64 = g_idx_is64;

    // ---- per-bag ranges ----
    if (tid < NB) {
        int bg = blockIdx.x * NB + tid;
        long long st = 0, en = 0;
        if (bg < nseg) {
            st = ld_idx(offsets, bg, is64);
            en = (bg + 1 < nseg) ? ld_idx(offsets, bg + 1, is64) : nnz;
        }
        long long c = en - st;
        if (c < 0) c = 0;
        if (c > MAXI) c = MAXI;
        s_cnt[tid]   = (int)c;
        s_start[tid] = st;
    }

    // ---- stage Wt (coalesced float4, conflict-free), AhT, Pb ----
    for (int q = tid; q < 64 * 16; q += NT) {       // 1024 float4s
        int d = q >> 4, c4 = q & 15;
        *reinterpret_cast<float4*>(Wt + d * PAD + c4 * 4) =
            reinterpret_cast<const float4*>(g_Wt)[q];
    }
    for (int p = tid; p < ATTm * KN; p += NT) {
        int a = p >> 2, k = p & 3;
        AhT[k * PAD + a] = atth[p];
    }
    if (tid < ATTm) Pb[tid] = projb[tid];
    __syncthreads();   // s_cnt ready for gather

    // ---- gather embeddings: 16 threads/row, float4 ----
    {
        const int c4 = tid & 15;
        for (int row = tid >> 4; row < NITEM; row += NT / 16) {
            int bag = row / MAXI;
            int it  = row - bag * MAXI;
            float4 v = make_float4(0.f, 0.f, 0.f, 0.f);
            if (it < s_cnt[bag]) {
                long long idx = ld_idx(input_, s_start[bag] + it, is64);
                v = reinterpret_cast<const float4*>(emb + idx * (long long)Dm)[c4];
            }
            *reinterpret_cast<float4*>(E + row * PAD + c4 * 4) = v;
        }
    }
    __syncthreads();   // E + Wt ready

    // ---- GEMM + fused attention logits ----
    // Thread: a-quad aq = tid&15 (a0 = 4*aq), item set i_r = ioct + 28*r.
    // Lanes in a warp: aq = lane&15 (a consecutive -> W conflict-free),
    //                  ioct differs by 1 (items consecutive -> E conflict-free).
    const int aq = tid & 15;
    const int a0 = aq << 2;
    const float4 pb4 = *reinterpret_cast<const float4*>(Pb + a0);
    const float4 ah0 = *reinterpret_cast<const float4*>(AhT + 0 * PAD + a0);
    const float4 ah1 = *reinterpret_cast<const float4*>(AhT + 1 * PAD + a0);
    const float4 ah2 = *reinterpret_cast<const float4*>(AhT + 2 * PAD + a0);
    const float4 ah3 = *reinterpret_cast<const float4*>(AhT + 3 * PAD + a0);

    #pragma unroll
    for (int pass = 0; pass < 2; ++pass) {
        const int ioct = pass * 14 + (tid >> 4);   // 0..27
        ull acc[8][2];
        #pragma unroll
        for (int r = 0; r < 8; ++r) { acc[r][0] = 0ull; acc[r][1] = 0ull; }

        const float* ep = E + ioct * PAD;          // item stride 28*PAD
        #pragma unroll 4
        for (int d = 0; d < 64; d += 4) {
            double2 w0 = *reinterpret_cast<const double2*>(Wt + (d+0)*PAD + a0);
            double2 w1 = *reinterpret_cast<const double2*>(Wt + (d+1)*PAD + a0);
            double2 w2 = *reinterpret_cast<const double2*>(Wt + (d+2)*PAD + a0);
            double2 w3 = *reinterpret_cast<const double2*>(Wt + (d+3)*PAD + a0);
            const ull w0l = __double_as_longlong(w0.x), w0h = __double_as_longlong(w0.y);
            const ull w1l = __double_as_longlong(w1.x), w1h = __double_as_longlong(w1.y);
            const ull w2l = __double_as_longlong(w2.x), w2h = __double_as_longlong(w2.y);
            const ull w3l = __double_as_longlong(w3.x), w3h = __double_as_longlong(w3.y);
            #pragma unroll
            for (int r = 0; r < 8; ++r) {
                float4 e = *reinterpret_cast<const float4*>(ep + r * (28 * PAD) + d);
                const ull ex = bcast2(e.x), ey = bcast2(e.y);
                const ull ez = bcast2(e.z), ew = bcast2(e.w);
                ffma2(acc[r][0], ex, w0l); ffma2(acc[r][1], ex, w0h);
                ffma2(acc[r][0], ey, w1l); ffma2(acc[r][1], ey, w1h);
                ffma2(acc[r][0], ez, w2l); ffma2(acc[r][1], ez, w2h);
                ffma2(acc[r][0], ew, w3l); ffma2(acc[r][1], ew, w3h);
            }
        }

        // epilogue: tanh + partial att, butterfly-reduce over the 16 aq lanes
        float p_att[8][KN];
        #pragma unroll
        for (int r = 0; r < 8; ++r) {
            float v0, v1, v2, v3;
            unpack2(v0, v1, acc[r][0]);
            unpack2(v2, v3, acc[r][1]);
            float h0 = tanh_fast(v0 + pb4.x);
            float h1 = tanh_fast(v1 + pb4.y);
            float h2 = tanh_fast(v2 + pb4.z);
            float h3 = tanh_fast(v3 + pb4.w);
            p_att[r][0] = h0*ah0.x + h1*ah0.y + h2*ah0.z + h3*ah0.w;
            p_att[r][1] = h0*ah1.x + h1*ah1.y + h2*ah1.z + h3*ah1.w;
            p_att[r][2] = h0*ah2.x + h1*ah2.y + h2*ah2.z + h3*ah2.w;
            p_att[r][3] = h0*ah3.x + h1*ah3.y + h2*ah3.z + h3*ah3.w;
        }
        #pragma unroll
        for (int off = 1; off <= 8; off <<= 1) {
            #pragma unroll
            for (int r = 0; r < 8; ++r) {
                #pragma unroll
                for (int k = 0; k < KN; ++k)
                    p_att[r][k] += __shfl_xor_sync(0xffffffffu, p_att[r][k], off);
            }
        }
        if (aq == 0) {
            #pragma unroll
            for (int r = 0; r < 8; ++r) {
                const int i = ioct + 28 * r;
                #pragma unroll
                for (int k = 0; k < KN; ++k) At[i * KN + k] = p_att[r][k];
            }
        }
    }
    __syncthreads();   // At ready

    // ---- ragged softmax: warp j handles bag j ----
    {
        const int w    = tid >> 5;
        const int lane = tid & 31;
        if (w < NB) {
            const int k = lane & 3, grp = lane >> 2;   // 8 item groups
            const int c = s_cnt[w];
            const float* ab = At + (w * MAXI) * KN + k;
            float m = -1e30f;
            #pragma unroll
            for (int it = 0; it < 7; ++it) {
                int i = grp + (it << 3);
                if (i < c) m = fmaxf(m, ab[i * KN]);
            }
            #pragma unroll
            for (int off = 4; off <= 16; off <<= 1)
                m = fmaxf(m, __shfl_xor_sync(0xffffffffu, m, off));
            float s = 0.f;
            #pragma unroll
            for (int it = 0; it < 7; ++it) {
                int i = grp + (it << 3);
                if (i < c) {
                    float e = __expf(ab[i * KN] - m);
                    At[(w * MAXI + i) * KN + k] = e;
                    s += e;
                }
            }
            #pragma unroll
            for (int off = 4; off <= 16; off <<= 1)
                s += __shfl_xor_sync(0xffffffffu, s, off);
            if (grp == 0) Red[w * KN + k] = (s > 0.f) ? 1.0f / s : 0.f;
        }
    }
    __syncthreads();   // normalized weights + Red ready

    // ---- pooling: 128 threads = 4 bags x 4 k x 8 d-octets ----
    if (tid < 128) {
        const int d8 = tid & 7;
        const int k  = (tid >> 3) & 3;
        const int j  = tid >> 5;
        const int bg = blockIdx.x * NB + j;
        if (bg < nseg) {
            const int c = s_cnt[j];
            const float* eb = E  + (j * MAXI) * PAD + d8 * 8;
            const float* ab = At + (j * MAXI) * KN + k;
            float4 A1 = make_float4(0,0,0,0), A2 = make_float4(0,0,0,0);
            for (int i = 0; i < c; ++i) {
                float wgt = ab[i * KN];
                float4 e1 = *reinterpret_cast<const float4*>(eb + i * PAD);
                float4 e2 = *reinterpret_cast<const float4*>(eb + i * PAD + 4);
                A1.x += wgt*e1.x; A1.y += wgt*e1.y; A1.z += wgt*e1.z; A1.w += wgt*e1.w;
                A2.x += wgt*e2.x; A2.y += wgt*e2.y; A2.z += wgt*e2.z; A2.w += wgt*e2.w;
            }
            const float inv = Red[j * KN + k];
            A1.x *= inv; A1.y *= inv; A1.z *= inv; A1.w *= inv;
            A2.x *= inv; A2.y *= inv; A2.z *= inv; A2.w *= inv;
            float* op = out + (size_t)bg * (KN * Dm) + k * Dm + d8 * 8;
            *reinterpret_cast<float4*>(op)     = A1;
            *reinterpret_cast<float4*>(op + 4) = A2;
        }
    }
}

extern "C" void kernel_launch(void* const* d_in, const int* in_sizes, int n_in,
                              void* d_out, int out_size) {
    const void*  input_  = d_in[0];
    const void*  offsets = d_in[1];
    const float* emb     = (const float*)d_in[2];
    const float* projw   = (const float*)d_in[3];
    const float* projb   = (const float*)d_in[4];
    const float* atth    = (const float*)d_in[5];
    float* out = (float*)d_out;

    const int       nseg  = in_sizes[1];
    const long long nnz   = in_sizes[0];
    const long long vocab = (long long)in_sizes[2] / Dm;

    prep_kernel<<<1, 256>>>(projw, input_, offsets, nnz, nseg, vocab);

    const size_t smem = SMEM_FLOATS * sizeof(float);  // ~83.4 KB
    cudaFuncSetAttribute(pooled_att_kernel,
                         cudaFuncAttributeMaxDynamicSharedMemorySize, (int)smem);
    const int grid = (nseg + NB - 1) / NB;
    pooled_att_kernel<<<grid, NT, smem>>>(input_, offsets, emb, projb,
                                          atth, out, nseg, nnz);
}

// round 5
// speedup vs baseline: 1.3102x; 1.3102x over previous
#include <cuda_runtime.h>

// Pooled attention embedding bag, GB300 (sm_103a).
//   B=8192 bags, L<=56/bag (via offsets), D=64, ATT=64, K=4.
//   out[b,k,:] = sum_i softmax_i( tanh(E_i @ Wp^T + b) @ att_h )[k] * E_i
//
// R5: 2 bags/CTA, 256 thr, ~50KB smem, <=64 regs -> 4 CTAs/SM (50% occ).
//  * E stored TRANSPOSED (ET[d][item], pad 116): double2 LDS delivers two
//    items pre-packed for fma.rn.f32x2 (item-packed accumulators).
//  * W transposed once in prep kernel into g_Wt; CTA stages it with
//    coalesced conflict-free float4 copies.
//  * Second GEMM (H @ att_h) fused into GEMM epilogue; 16-lane reduction by
//    compress-split shuffles (8 SHFL per item-pair instead of 32).
//  * Warp softmax per bag; k-packed f32x2 pooling reading ET.

namespace {
constexpr int Dm    = 64;
constexpr int ATTm  = 64;
constexpr int KN    = 4;
constexpr int NB    = 2;               // bags per CTA
constexpr int MAXI  = 56;              // items staged per bag
constexpr int NITEM = NB * MAXI;       // 112
constexpr int NPAIR = NITEM / 2;       // 56
constexpr int PADW  = 68;              // W row pad (floats)
constexpr int PADN  = 116;             // ET row pad (floats, even for 8B loads)
constexpr int NT    = 256;
constexpr int SMEM_FLOATS = 64*PADW    // Wt [d][a]
                          + 64*PADN    // ET [d][item]
                          + NITEM*KN   // At [item][k]
                          + KN*PADW    // AhT[k][a]
                          + ATTm       // Pb
                          + 8;         // Red [bag][k] = 1/sum
}

__device__ int   g_idx_is64;
__device__ float g_Wt[64 * 64];        // g_Wt[d*64+a] = projw[a*64+d]

using ull = unsigned long long;

__device__ __forceinline__ float tanh_fast(float x) {
    float y; asm("tanh.approx.f32 %0, %1;" : "=f"(y) : "f"(x)); return y;
}
__device__ __forceinline__ void ffma2(ull& d, ull a, ull b) {
    asm("fma.rn.f32x2 %0, %1, %2, %0;" : "+l"(d) : "l"(a), "l"(b));
}
__device__ __forceinline__ ull bcast2(float x) {
    ull r; asm("mov.b64 %0, {%1, %1};" : "=l"(r) : "f"(x)); return r;
}
__device__ __forceinline__ void unpack2(float& lo, float& hi, ull v) {
    asm("mov.b64 {%0, %1}, %2;" : "=f"(lo), "=f"(hi) : "l"(v));
}
__device__ __forceinline__ long long ld_idx(const void* p, long long i, int is64) {
    return is64 ? ((const long long*)p)[i] : (long long)((const int*)p)[i];
}

extern "C" __global__ void prep_kernel(const float* __restrict__ projw,
                                       const void* __restrict__ input_,
                                       const void* __restrict__ offsets,
                                       long long nnz, int nseg, long long vocab) {
    int t = threadIdx.x;
    for (int p = t; p < 64 * 64; p += 256) {
        int a = p >> 6, d = p & 63;
        g_Wt[d * 64 + a] = projw[p];
    }
    if (t == 0) {
        bool ok = true;
        const long long* o64 = (const long long*)offsets;
        int no = nseg < 4 ? nseg : 4;
        long long prev = -1;
        for (int i = 0; i < no; ++i) {
            long long v = o64[i];
            if (v < 0 || v > nnz || v < prev) ok = false;
            prev = v;
        }
        const long long* in64 = (const long long*)input_;
        long long ni = nnz < 8 ? nnz : 8;
        for (long long i = 0; i < ni; ++i) {
            long long v = in64[i];
            if (v < 0 || v >= vocab) ok = false;
        }
        g_idx_is64 = ok ? 1 : 0;
    }
}

extern "C" __global__ void __launch_bounds__(NT, 4)
pooled_att_kernel(const void*  __restrict__ input_,
                  const void*  __restrict__ offsets,
                  const float* __restrict__ emb,
                  const float* __restrict__ projb,
                  const float* __restrict__ atth,
                  float*       __restrict__ out,
                  int nseg, long long nnz)
{
    extern __shared__ float sm[];
    float* Wt  = sm;                    // [64][PADW]
    float* ET  = Wt  + 64*PADW;         // [64][PADN]  ET[d*PADN+item]
    float* At  = ET  + 64*PADN;         // [NITEM][KN]
    float* AhT = At  + NITEM*KN;        // [KN][PADW]
    float* Pb  = AhT + KN*PADW;         // [64]
    float* Red = Pb  + ATTm;            // [NB][KN]

    __shared__ long long s_start[NB];
    __shared__ int       s_cnt[NB];

    const int tid  = threadIdx.x;
    const int is64 = g_idx_is64;

    if (tid < NB) {
        int bg = blockIdx.x * NB + tid;
        long long st = 0, en = 0;
        if (bg < nseg) {
            st = ld_idx(offsets, bg, is64);
            en = (bg + 1 < nseg) ? ld_idx(offsets, bg + 1, is64) : nnz;
        }
        long long c = en - st;
        if (c < 0) c = 0;
        if (c > MAXI) c = MAXI;
        s_cnt[tid]   = (int)c;
        s_start[tid] = st;
    }
    // stage Wt (coalesced float4), AhT, Pb
    for (int q = tid; q < 64 * 16; q += NT) {
        int d = q >> 4, c4 = q & 15;
        *reinterpret_cast<float4*>(Wt + d * PADW + c4 * 4) =
            reinterpret_cast<const float4*>(g_Wt)[q];
    }
    if (tid < ATTm * KN) {
        int a = tid >> 2, k = tid & 3;
        AhT[k * PADW + a] = atth[tid];
    }
    if (tid < ATTm) Pb[tid] = projb[tid];
    __syncthreads();                    // s_cnt ready

    // gather embeddings into ET (transposed scatter)
    {
        const int c4 = tid & 15;
        const int d0 = c4 * 4;
        for (int row = tid >> 4; row < NITEM; row += NT / 16) {
            int bag = (row >= MAXI) ? 1 : 0;
            int it  = row - bag * MAXI;
            float4 v = make_float4(0.f, 0.f, 0.f, 0.f);
            if (it < s_cnt[bag]) {
                long long idx = ld_idx(input_, s_start[bag] + it, is64);
                v = reinterpret_cast<const float4*>(emb + idx * (long long)Dm)[c4];
            }
            ET[(d0 + 0) * PADN + row] = v.x;
            ET[(d0 + 1) * PADN + row] = v.y;
            ET[(d0 + 2) * PADN + row] = v.z;
            ET[(d0 + 3) * PADN + row] = v.w;
        }
    }
    __syncthreads();                    // ET + Wt ready

    // ---- GEMM: item-pair-packed f32x2; thread = (a-quad aq, pair-group pg) ----
    const int aq = tid & 15;
    const int pg = tid >> 4;            // 0..15 ; pairs pg+16r, r<4 (r=3 ragged)
    const bool v3 = (pg + 48) < NPAIR;
    const int off3 = v3 ? 96 : 0;       // clamped (discarded) for invalid r=3

    ull acc[4][4];                      // [a][r]
    #pragma unroll
    for (int a = 0; a < 4; ++a)
        #pragma unroll
        for (int r = 0; r < 4; ++r) acc[a][r] = 0ull;

    {
        const float* wrow = Wt + 4 * aq;
        const float* erow = ET + 2 * pg;
        #pragma unroll 8
        for (int d = 0; d < 64; ++d) {
            float4 wq = *reinterpret_cast<const float4*>(wrow + d * PADW);
            ull w0 = bcast2(wq.x), w1 = bcast2(wq.y);
            ull w2 = bcast2(wq.z), w3 = bcast2(wq.w);
            const float* er = erow + d * PADN;
            ull e0 = *reinterpret_cast<const ull*>(er);
            ull e1 = *reinterpret_cast<const ull*>(er + 32);
            ull e2 = *reinterpret_cast<const ull*>(er + 64);
            ull e3 = *reinterpret_cast<const ull*>(er + off3);
            ffma2(acc[0][0], w0, e0); ffma2(acc[1][0], w1, e0);
            ffma2(acc[2][0], w2, e0); ffma2(acc[3][0], w3, e0);
            ffma2(acc[0][1], w0, e1); ffma2(acc[1][1], w1, e1);
            ffma2(acc[2][1], w2, e1); ffma2(acc[3][1], w3, e1);
            ffma2(acc[0][2], w0, e2); ffma2(acc[1][2], w1, e2);
            ffma2(acc[2][2], w2, e2); ffma2(acc[3][2], w3, e2);
            ffma2(acc[0][3], w0, e3); ffma2(acc[1][3], w1, e3);
            ffma2(acc[2][3], w2, e3); ffma2(acc[3][3], w3, e3);
        }
    }

    // ---- epilogue: tanh + (H @ att_h) + 16-lane compress-split reduction ----
    {
        const int a0 = 4 * aq;
        float pb0 = Pb[a0], pb1 = Pb[a0+1], pb2 = Pb[a0+2], pb3 = Pb[a0+3];
        const bool u8 = (aq & 8) != 0, u4 = (aq & 4) != 0, u2 = (aq & 2) != 0;
        const int j  = (u8 ? 4 : 0) | (u4 ? 2 : 0) | (u2 ? 1 : 0);
        const int kk = j & 3, hh = j >> 2;

        #pragma unroll
        for (int r = 0; r < 4; ++r) {
            float lo0, hi0, lo1, hi1, lo2, hi2, lo3, hi3;
            unpack2(lo0, hi0, acc[0][r]); unpack2(lo1, hi1, acc[1][r]);
            unpack2(lo2, hi2, acc[2][r]); unpack2(lo3, hi3, acc[3][r]);
            float hl0 = tanh_fast(lo0 + pb0), hh0 = tanh_fast(hi0 + pb0);
            float hl1 = tanh_fast(lo1 + pb1), hh1 = tanh_fast(hi1 + pb1);
            float hl2 = tanh_fast(lo2 + pb2), hh2 = tanh_fast(hi2 + pb2);
            float hl3 = tanh_fast(lo3 + pb3), hh3 = tanh_fast(hi3 + pb3);

            float v[8];
            #pragma unroll
            for (int k = 0; k < 4; ++k) {
                float4 ah = *reinterpret_cast<const float4*>(AhT + k * PADW + a0);
                v[k]     = hl0*ah.x + hl1*ah.y + hl2*ah.z + hl3*ah.w;
                v[4 + k] = hh0*ah.x + hh1*ah.y + hh2*ah.z + hh3*ah.w;
            }
            // level xor 8: 8 -> 4 values
            float s0, s1, s2, s3;
            {
                float t0 = u8 ? v[0] : v[4];
                float t1 = u8 ? v[1] : v[5];
                float t2 = u8 ? v[2] : v[6];
                float t3 = u8 ? v[3] : v[7];
                s0 = (u8 ? v[4] : v[0]) + __shfl_xor_sync(0xffffffffu, t0, 8);
                s1 = (u8 ? v[5] : v[1]) + __shfl_xor_sync(0xffffffffu, t1, 8);
                s2 = (u8 ? v[6] : v[2]) + __shfl_xor_sync(0xffffffffu, t2, 8);
                s3 = (u8 ? v[7] : v[3]) + __shfl_xor_sync(0xffffffffu, t3, 8);
            }
            // level xor 4: 4 -> 2
            float q0, q1;
            {
                float t0 = u4 ? s0 : s2;
                float t1 = u4 ? s1 : s3;
                q0 = (u4 ? s2 : s0) + __shfl_xor_sync(0xffffffffu, t0, 4);
                q1 = (u4 ? s3 : s1) + __shfl_xor_sync(0xffffffffu, t1, 4);
            }
            // level xor 2: 2 -> 1
            float t = u2 ? q0 : q1;
            float w = (u2 ? q1 : q0) + __shfl_xor_sync(0xffffffffu, t, 2);
            // level xor 1: duplicate-class full add
            w += __shfl_xor_sync(0xffffffffu, w, 1);

            const int p = pg + 16 * r;
            if ((aq & 1) == 0 && p < NPAIR)
                At[(2 * p + hh) * KN + kk] = w;
        }
    }
    __syncthreads();                    // At ready

    // ---- ragged softmax: warp j -> bag j ----
    {
        const int w    = tid >> 5;
        const int lane = tid & 31;
        if (w < NB) {
            const int k = lane & 3, grp = lane >> 2;
            const int c = s_cnt[w];
            float* ab = At + (w * MAXI) * KN + k;
            float m = -1e30f;
            #pragma unroll
            for (int it = 0; it < 7; ++it) {
                int i = grp + (it << 3);
                if (i < c) m = fmaxf(m, ab[i * KN]);
            }
            #pragma unroll
            for (int off = 4; off <= 16; off <<= 1)
                m = fmaxf(m, __shfl_xor_sync(0xffffffffu, m, off));
            float s = 0.f;
            #pragma unroll
            for (int it = 0; it < 7; ++it) {
                int i = grp + (it << 3);
                if (i < c) {
                    float e = __expf(ab[i * KN] - m);
                    ab[i * KN] = e;
                    s += e;
                }
            }
            #pragma unroll
            for (int off = 4; off <= 16; off <<= 1)
                s += __shfl_xor_sync(0xffffffffu, s, off);
            if (grp == 0) Red[w * KN + k] = (s > 0.f) ? 1.0f / s : 0.f;
        }
    }
    __syncthreads();                    // weights + Red ready

    // ---- pooling: 128 threads = 2 bags x 64 d; k-packed f32x2 ----
    if (tid < 128) {
        const int b  = tid >> 6;
        const int d  = tid & 63;
        const int bg = blockIdx.x * NB + b;
        if (bg < nseg) {
            const int c = s_cnt[b];
            const float* ep = ET + d * PADN + b * MAXI;
            const float* ap = At + (b * MAXI) * KN;
            ull a01 = 0ull, a23 = 0ull;
            for (int i = 0; i < c; ++i) {
                ull e2 = bcast2(ep[i]);
                ull w01 = *reinterpret_cast<const ull*>(ap + i * KN);
                ull w23 = *reinterpret_cast<const ull*>(ap + i * KN + 2);
                ffma2(a01, e2, w01);
                ffma2(a23, e2, w23);
            }
            float r0, r1, r2, r3;
            unpack2(r0, r1, a01);
            unpack2(r2, r3, a23);
            float* op = out + (size_t)bg * (KN * Dm) + d;
            op[0]        = r0 * Red[b * KN + 0];
            op[Dm]       = r1 * Red[b * KN + 1];
            op[2 * Dm]   = r2 * Red[b * KN + 2];
            op[3 * Dm]   = r3 * Red[b * KN + 3];
        }
    }
}

extern "C" void kernel_launch(void* const* d_in, const int* in_sizes, int n_in,
                              void* d_out, int out_size) {
    const void*  input_  = d_in[0];
    const void*  offsets = d_in[1];
    const float* emb     = (const float*)d_in[2];
    const float* projw   = (const float*)d_in[3];
    const float* projb   = (const float*)d_in[4];
    const float* atth    = (const float*)d_in[5];
    float* out = (float*)d_out;

    const int       nseg  = in_sizes[1];
    const long long nnz   = in_sizes[0];
    const long long vocab = (long long)in_sizes[2] / Dm;

    prep_kernel<<<1, 256>>>(projw, input_, offsets, nnz, nseg, vocab);

    const size_t smem = SMEM_FLOATS * sizeof(float);  // ~50.3 KB
    cudaFuncSetAttribute(pooled_att_kernel,
                         cudaFuncAttributeMaxDynamicSharedMemorySize, (int)smem);
    const int grid = (nseg + NB - 1) / NB;
    pooled_att_kernel<<<grid, NT, smem>>>(input_, offsets, emb, projb,
                                          atth, out, nseg, nnz);
}